// round 14
// baseline (speedup 1.0000x reference)
#include <cuda_runtime.h>
#include <cuda_fp16.h>
#include <cstdint>

// Problem constants (fixed by setup_inputs)
#define Bb    2
#define Tt    2048
#define Cc    1024
#define QLd   128
#define KVL   128
#define NHh   16
#define HSd   64
#define BT    (Bb*Tt)          // 4096

// Scratch (device globals: no allocation allowed)
__device__ float g_P [QLd*KVL];
__device__ float g_M [Cc*KVL];
__device__ float g_Nt[NHh*KVL*QLd];
__device__ float g_R [Cc*KVL];
__device__ float g_Aq[BT*QLd];
__device__ float g_ql[NHh*BT*KVL];       // holds fp16 latent queries (prescaled)
__device__ float g_ct[NHh*BT*KVL];       // latent context (also GEMM partial scratch)
__device__ __half g_kh [Bb*Tt*KVL];      // ckv fp16, s-major  [b][s][d]
__device__ __half g_khT[Bb*KVL*Tt];      // ckv fp16, d-major  [b][d][s]

#define QSCALE 0.18033688011112f         // 0.125 * log2(e)

__device__ __forceinline__ uint32_t f2h2(float a, float b) {
    __half2 h = __floats2half2_rn(a, b);
    return *(uint32_t*)&h;
}
__device__ __forceinline__ void mma_f16(float* d, const uint32_t* a, uint32_t b0, uint32_t b1) {
    asm volatile(
        "mma.sync.aligned.m16n8k16.row.col.f32.f16.f16.f32 "
        "{%0,%1,%2,%3}, {%4,%5,%6,%7}, {%8,%9}, {%0,%1,%2,%3};"
        : "+f"(d[0]), "+f"(d[1]), "+f"(d[2]), "+f"(d[3])
        : "r"(a[0]), "r"(a[1]), "r"(a[2]), "r"(a[3]), "r"(b0), "r"(b1));
}

// ===========================================================================
// fp16 tensor-core GEMM, software-pipelined, double-buffered (R12 + HOUT).
// HOUT: epilogue scales by oscale and stores __half. NOTE: sC stays in
// FLOAT units (the z-advance happens on the float* base) — callers using
// HOUT with batching must pass the half-stride/2.
// ===========================================================================
template<int BN, bool NN, bool COMP, bool HOUT>
__global__ __launch_bounds__(256)
void hgemm(const float* __restrict__ A, const float* __restrict__ B,
           float* __restrict__ C, const float* __restrict__ B2,
           float* __restrict__ C2, int K,
           int lda, int ldb, int ldc, long sA, long sB, long sC, int nb1,
           float oscale)
{
    constexpr int BM = 128, AW = BM * 20, BW = BN * 20;
    constexpr int NF = BN / 16;
    constexpr int STG = (COMP ? 2 : 1) * (AW + BW);
    constexpr int NA4 = BM * 8 / 256;
    constexpr int NB4 = BN * 8 / 256;
    extern __shared__ uint32_t sh[];

    const int z = blockIdx.z;
    A += (long)z * sA;
    const float* Bp = B;  float* Cp = C;
    int by = blockIdx.y;
    if (by >= nb1) { Bp = B2; Cp = C2; by -= nb1; }
    Bp += (long)z * sB;  Cp += (long)z * sC;

    const int m0 = blockIdx.x * BM, n0 = by * BN;
    const int t = threadIdx.x;
    const int wid = t >> 5, g = (t & 31) >> 2, tid = t & 3;
    const int wm = wid >> 1, wn = wid & 1;

    float accH[2][NF][4];
    float accL[COMP ? 2 : 1][COMP ? NF : 1][4];
    #pragma unroll
    for (int i = 0; i < 2; i++)
        #pragma unroll
        for (int j = 0; j < NF; j++)
            #pragma unroll
            for (int q = 0; q < 4; q++) {
                accH[i][j][q] = 0.f;
                if (COMP) accL[i][j][q] = 0.f;
            }

    float4 aR[NA4], bR[NB4];

    auto loadTile = [&](int k0) {
        #pragma unroll
        for (int i = 0; i < NA4; i++) {
            int idx = t + i * 256;
            int r = idx >> 3, c4 = (idx & 7) * 4;
            aR[i] = *(const float4*)(A + (long)(m0 + r) * lda + k0 + c4);
        }
        if (!NN) {
            #pragma unroll
            for (int i = 0; i < NB4; i++) {
                int idx = t + i * 256;
                int r = idx >> 3, c4 = (idx & 7) * 4;
                bR[i] = *(const float4*)(Bp + (long)(n0 + r) * ldb + k0 + c4);
            }
        } else {
            #pragma unroll
            for (int i = 0; i < NB4; i++) {
                int idx = t + i * 256;
                int kr = idx / (BN / 4);
                int nn = (idx % (BN / 4)) * 4;
                bR[i] = *(const float4*)(Bp + (long)(k0 + kr) * ldb + n0 + nn);
            }
        }
    };
    auto storeTile = [&](int s) {
        uint32_t* Ah = sh + s * STG;
        uint32_t* Bh = Ah + AW;
        uint32_t* Al = Bh + BW;
        uint32_t* Bl = Al + AW;
        #pragma unroll
        for (int i = 0; i < NA4; i++) {
            int idx = t + i * 256;
            int r = idx >> 3, c4 = (idx & 7) * 4;
            float4 v = aR[i];
            uint32_t h0 = f2h2(v.x, v.y), h1 = f2h2(v.z, v.w);
            Ah[r * 20 + (c4 >> 1)]     = h0;
            Ah[r * 20 + (c4 >> 1) + 1] = h1;
            if (COMP) {
                __half2 p0 = *(__half2*)&h0, p1 = *(__half2*)&h1;
                float2 f0 = __half22float2(p0), f1 = __half22float2(p1);
                Al[r * 20 + (c4 >> 1)]     = f2h2((v.x - f0.x) * 1024.f, (v.y - f0.y) * 1024.f);
                Al[r * 20 + (c4 >> 1) + 1] = f2h2((v.z - f1.x) * 1024.f, (v.w - f1.y) * 1024.f);
            }
        }
        if (!NN) {
            #pragma unroll
            for (int i = 0; i < NB4; i++) {
                int idx = t + i * 256;
                int r = idx >> 3, c4 = (idx & 7) * 4;
                float4 v = bR[i];
                uint32_t h0 = f2h2(v.x, v.y), h1 = f2h2(v.z, v.w);
                Bh[r * 20 + (c4 >> 1)]     = h0;
                Bh[r * 20 + (c4 >> 1) + 1] = h1;
                if (COMP) {
                    __half2 p0 = *(__half2*)&h0, p1 = *(__half2*)&h1;
                    float2 f0 = __half22float2(p0), f1 = __half22float2(p1);
                    Bl[r * 20 + (c4 >> 1)]     = f2h2((v.x - f0.x) * 1024.f, (v.y - f0.y) * 1024.f);
                    Bl[r * 20 + (c4 >> 1) + 1] = f2h2((v.z - f1.x) * 1024.f, (v.w - f1.y) * 1024.f);
                }
            }
        } else {
            __half* Bhh = (__half*)Bh;
            #pragma unroll
            for (int i = 0; i < NB4; i++) {
                int idx = t + i * 256;
                int kr = idx / (BN / 4);
                int nn = (idx % (BN / 4)) * 4;
                float4 v = bR[i];
                Bhh[(nn + 0) * 40 + kr] = __float2half_rn(v.x);
                Bhh[(nn + 1) * 40 + kr] = __float2half_rn(v.y);
                Bhh[(nn + 2) * 40 + kr] = __float2half_rn(v.z);
                Bhh[(nn + 3) * 40 + kr] = __float2half_rn(v.w);
            }
        }
    };

    const int nk = K / 32;
    loadTile(0);
    storeTile(0);
    __syncthreads();

    for (int it = 0; it < nk; it++) {
        if (it + 1 < nk) loadTile(32 * (it + 1));

        const uint32_t* Ah = sh + (it & 1) * STG;
        const uint32_t* Bh = Ah + AW;
        const uint32_t* Al = Bh + BW;
        const uint32_t* Bl = Al + AW;

        #pragma unroll
        for (int s = 0; s < 2; s++) {
            const int kk = 8 * s + tid;
            uint32_t ah[2][4], al[2][4];
            #pragma unroll
            for (int mf = 0; mf < 2; mf++) {
                int r = wm * 32 + 16 * mf + g;
                ah[mf][0] = Ah[r * 20 + kk];       ah[mf][1] = Ah[(r + 8) * 20 + kk];
                ah[mf][2] = Ah[r * 20 + kk + 4];   ah[mf][3] = Ah[(r + 8) * 20 + kk + 4];
                if (COMP) {
                    al[mf][0] = Al[r * 20 + kk];     al[mf][1] = Al[(r + 8) * 20 + kk];
                    al[mf][2] = Al[r * 20 + kk + 4]; al[mf][3] = Al[(r + 8) * 20 + kk + 4];
                }
            }
            #pragma unroll
            for (int nf = 0; nf < NF; nf++) {
                int n = wn * (BN / 2) + 8 * nf + g;
                uint32_t b0 = Bh[n * 20 + kk], b1 = Bh[n * 20 + kk + 4];
                #pragma unroll
                for (int mf = 0; mf < 2; mf++) {
                    mma_f16(accH[mf][nf], ah[mf], b0, b1);
                    if (COMP) mma_f16(accL[mf][nf], al[mf], b0, b1);
                }
                if (COMP) {
                    uint32_t c0 = Bl[n * 20 + kk], c1 = Bl[n * 20 + kk + 4];
                    #pragma unroll
                    for (int mf = 0; mf < 2; mf++)
                        mma_f16(accL[mf][nf], ah[mf], c0, c1);
                }
            }
        }

        if (it + 1 < nk) storeTile((it + 1) & 1);
        __syncthreads();
    }

    const float lsc = 1.f / 1024.f;
    #pragma unroll
    for (int mf = 0; mf < 2; mf++) {
        const int r0 = m0 + wm * 32 + 16 * mf + g;
        #pragma unroll
        for (int nf = 0; nf < NF; nf++) {
            const int c = n0 + wn * (BN / 2) + 8 * nf + 2 * tid;
            float v0 = accH[mf][nf][0], v1 = accH[mf][nf][1];
            float v2 = accH[mf][nf][2], v3 = accH[mf][nf][3];
            if (COMP) {
                v0 += accL[mf][nf][0] * lsc;  v1 += accL[mf][nf][1] * lsc;
                v2 += accL[mf][nf][2] * lsc;  v3 += accL[mf][nf][3] * lsc;
            }
            if (HOUT) {
                __half* Ch = (__half*)Cp;
                __half2 h0 = __floats2half2_rn(v0 * oscale, v1 * oscale);
                __half2 h1 = __floats2half2_rn(v2 * oscale, v3 * oscale);
                *(__half2*)(Ch + (long)r0 * ldc + c)       = h0;
                *(__half2*)(Ch + (long)(r0 + 8) * ldc + c) = h1;
            } else {
                *(float2*)(Cp + (long)r0 * ldc + c)       = make_float2(v0, v1);
                *(float2*)(Cp + (long)(r0 + 8) * ldc + c) = make_float2(v2, v3);
            }
        }
    }
}

// Split-K partial reduction (float4-wide)
__global__ __launch_bounds__(256)
void reduce_add(const float* __restrict__ src, float* __restrict__ dst,
                int n4, int parts, long pstride4)
{
    int i = blockIdx.x * blockDim.x + threadIdx.x;
    if (i >= n4) return;
    const float4* s = (const float4*)src;
    float4 acc = s[i];
    for (int p = 1; p < parts; p++) {
        float4 v = s[i + (long)p * pstride4];
        acc.x += v.x; acc.y += v.y; acc.z += v.z; acc.w += v.w;
    }
    ((float4*)dst)[i] = acc;
}

// ===========================================================================
// ckv -> fp16 one-shot conversion, both layouts (unchanged)
// ===========================================================================
__global__ __launch_bounds__(256)
void cvt_kernel(const float* __restrict__ ckv, __half* __restrict__ kh,
                __half* __restrict__ khT)
{
    __shared__ __half sm[128 * 132];
    const int st = blockIdx.x, b = blockIdx.y;
    const float* src = ckv + ((long)b * Tt + st * 128) * 128;
    __half* dsh = kh + ((long)b * Tt + st * 128) * 128;
    const int t = threadIdx.x;

    #pragma unroll
    for (int i = 0; i < 16; i++) {
        int idx = t + i * 256;
        int r = idx >> 5, c = (idx & 31) * 4;
        float4 v = *(const float4*)(src + (long)r * 128 + c);
        uint2 u = make_uint2(f2h2(v.x, v.y), f2h2(v.z, v.w));
        *(uint2*)(dsh + (long)r * 128 + c) = u;
        *(uint2*)(sm + r * 132 + c) = u;
    }
    __syncthreads();

    #pragma unroll
    for (int i = 0; i < 16; i++) {
        int idx = t + i * 256;
        int d = idx >> 5, sg = (idx & 31) * 4;
        __half h0 = sm[(sg + 0) * 132 + d];
        __half h1 = sm[(sg + 1) * 132 + d];
        __half h2 = sm[(sg + 2) * 132 + d];
        __half h3 = sm[(sg + 3) * 132 + d];
        uint2 u;
        __half2 p0 = __halves2half2(h0, h1);
        __half2 p1 = __halves2half2(h2, h3);
        u.x = *(uint32_t*)&p0;  u.y = *(uint32_t*)&p1;
        *(uint2*)(khT + ((long)b * 128 + d) * Tt + st * 128 + sg) = u;
    }
}

// ===========================================================================
// Tiny fp32-exact precompute kernels (unchanged)
// ===========================================================================
__global__ __launch_bounds__(128)
void pk_kernel(const float* __restrict__ W_uq, const float* __restrict__ W_uk,
               float* __restrict__ P)
{
    const int i = blockIdx.x, j = threadIdx.x;
    float s = 0.f;
    #pragma unroll 8
    for (int c = 0; c < 1024; c++)
        s += W_uq[c * 128 + i] * W_uk[c * 128 + j];
    P[i * 128 + j] = s;
}
__global__ __launch_bounds__(128)
void m_kernel(const float* __restrict__ W_dq, const float* __restrict__ P,
              float* __restrict__ M)
{
    const int c = blockIdx.x, j = threadIdx.x;
    float s = 0.f;
    #pragma unroll 8
    for (int i = 0; i < 128; i++)
        s += W_dq[i * 1024 + c] * P[i * 128 + j];
    M[c * 128 + j] = s;
}
__global__ __launch_bounds__(128)
void n_kernel(const float* __restrict__ W_uq, const float* __restrict__ M,
              float* __restrict__ Nt)
{
    const int j = blockIdx.x, h = blockIdx.y, i = threadIdx.x;
    float s = 0.f;
    #pragma unroll 8
    for (int d = 0; d < 64; d++)
        s += W_uq[(h * 64 + d) * 128 + i] * M[(h * 64 + d) * 128 + j];
    Nt[(h * 128 + j) * 128 + i] = s;
}

// ===========================================================================
// fp16 mma flash attention v8 (identical to R13; data handoff now correct).
// CTA: 128 queries, 4 warps x 32 rows (mf=2). Q in smem fp16 (prescaled by
// 0.125*log2e; softmax in exp2 domain). 128-key tiles as two 64-key subtiles;
// warps 0-1 skip the fully-masked upper subtile on the diagonal.
// Smem: Q + K1 + KT = 104448 B -> 2 CTAs/SM.
// ===========================================================================
#define A8_Q  0
#define A8_K1 (128 * 68)
#define A8_KT (2 * 128 * 68)
#define A8_WORDS (3 * 128 * 68)     // 26112 words = 104448 B

__global__ __launch_bounds__(128, 2)
void attn8_kernel(const __half* __restrict__ qlh, const __half* __restrict__ khG,
                  const __half* __restrict__ khTG, float* __restrict__ ctx)
{
    extern __shared__ uint32_t smu[];
    const int t = threadIdx.x;
    const int w = t >> 5, lid = t & 31;
    const int g = lid >> 2, tid = lid & 3;

    const int h  = blockIdx.x;
    const int qt = 15 - blockIdx.y;
    const int b  = blockIdx.z;
    const long qbase = ((long)h * BT + (long)b * Tt + (long)qt * 128) * 128;

    {
        const __half* qs = qlh + qbase;
        #pragma unroll
        for (int i = 0; i < 16; i++) {
            int idx = t + i * 128;
            int r = idx >> 4, c = idx & 15;
            *(uint4*)(smu + A8_Q + r * 68 + c * 4) =
                *(const uint4*)(qs + (long)r * 128 + c * 8);
        }
    }

    float oacc[2][16][4];
    #pragma unroll
    for (int mf = 0; mf < 2; mf++)
        #pragma unroll
        for (int nb = 0; nb < 16; nb++)
            #pragma unroll
            for (int q = 0; q < 4; q++) oacc[mf][nb][q] = 0.f;

    float m_run[2][2] = {{-1e30f, -1e30f}, {-1e30f, -1e30f}};
    float l_run[2][2] = {{0.f, 0.f}, {0.f, 0.f}};

    const int rw0 = 32 * w;

    for (int kt = 0; kt <= qt; kt++) {
        __syncthreads();
        {
            const __half* kh  = khG  + ((long)b * Tt + (long)kt * 128) * 128;
            const __half* khT = khTG + (long)b * 128 * Tt + (long)kt * 128;
            #pragma unroll
            for (int i = 0; i < 16; i++) {
                int idx = t + i * 128;
                int r = idx >> 4, c = idx & 15;
                *(uint4*)(smu + A8_K1 + r * 68 + c * 4) =
                    *(const uint4*)(kh + (long)r * 128 + c * 8);
            }
            #pragma unroll
            for (int i = 0; i < 16; i++) {
                int idx = t + i * 128;
                int d = idx >> 4, c = idx & 15;
                *(uint4*)(smu + A8_KT + d * 68 + c * 4) =
                    *(const uint4*)(khT + (long)d * Tt + c * 8);
            }
        }
        __syncthreads();

        const bool diag = (kt == qt);

        #pragma unroll
        for (int st = 0; st < 2; st++) {
            if (diag && st == 1 && w < 2) continue;   // fully masked subtile

            float sacc[2][8][4];
            #pragma unroll
            for (int mf = 0; mf < 2; mf++)
                #pragma unroll
                for (int nb = 0; nb < 8; nb++)
                    #pragma unroll
                    for (int q = 0; q < 4; q++) sacc[mf][nb][q] = 0.f;

            #pragma unroll
            for (int kb = 0; kb < 8; kb++) {
                const int w0 = 8 * kb + tid;
                uint32_t a[2][4];
                #pragma unroll
                for (int mf = 0; mf < 2; mf++) {
                    const int r = rw0 + 16 * mf + g;
                    a[mf][0] = smu[A8_Q + r * 68 + w0];
                    a[mf][1] = smu[A8_Q + (r + 8) * 68 + w0];
                    a[mf][2] = smu[A8_Q + r * 68 + w0 + 4];
                    a[mf][3] = smu[A8_Q + (r + 8) * 68 + w0 + 4];
                }
                #pragma unroll
                for (int nb = 0; nb < 8; nb++) {
                    const int rk = 64 * st + 8 * nb + g;
                    uint32_t b0 = smu[A8_K1 + rk * 68 + w0];
                    uint32_t b1 = smu[A8_K1 + rk * 68 + w0 + 4];
                    mma_f16(sacc[0][nb], a[0], b0, b1);
                    mma_f16(sacc[1][nb], a[1], b0, b1);
                }
            }

            if (diag) {
                #pragma unroll
                for (int mf = 0; mf < 2; mf++) {
                    const int rl = rw0 + 16 * mf + g;
                    #pragma unroll
                    for (int nb = 0; nb < 8; nb++)
                        #pragma unroll
                        for (int j = 0; j < 2; j++) {
                            const int col = 64 * st + 8 * nb + 2 * tid + j;
                            if (col > rl)     sacc[mf][nb][j]     = -1e30f;
                            if (col > rl + 8) sacc[mf][nb][2 + j] = -1e30f;
                        }
                }
            }

            #pragma unroll
            for (int mf = 0; mf < 2; mf++)
                #pragma unroll
                for (int hh = 0; hh < 2; hh++) {
                    float mt = -1e30f;
                    #pragma unroll
                    for (int nb = 0; nb < 8; nb++)
                        mt = fmaxf(mt, fmaxf(sacc[mf][nb][2 * hh], sacc[mf][nb][2 * hh + 1]));
                    mt = fmaxf(mt, __shfl_xor_sync(0xffffffffu, mt, 1));
                    mt = fmaxf(mt, __shfl_xor_sync(0xffffffffu, mt, 2));

                    const float mn = fmaxf(m_run[mf][hh], mt);
                    const float sc = exp2f(m_run[mf][hh] - mn);
                    float ls = 0.f;
                    #pragma unroll
                    for (int nb = 0; nb < 8; nb++) {
                        float p0 = exp2f(sacc[mf][nb][2 * hh]     - mn);
                        float p1 = exp2f(sacc[mf][nb][2 * hh + 1] - mn);
                        ls += p0 + p1;
                        sacc[mf][nb][2 * hh]     = p0;
                        sacc[mf][nb][2 * hh + 1] = p1;
                    }
                    ls += __shfl_xor_sync(0xffffffffu, ls, 1);
                    ls += __shfl_xor_sync(0xffffffffu, ls, 2);
                    l_run[mf][hh] = l_run[mf][hh] * sc + ls;
                    m_run[mf][hh] = mn;
                    #pragma unroll
                    for (int nb = 0; nb < 16; nb++) {
                        oacc[mf][nb][2 * hh]     *= sc;
                        oacc[mf][nb][2 * hh + 1] *= sc;
                    }
                }

            #pragma unroll
            for (int kb = 0; kb < 4; kb++) {
                uint32_t af[2][4];
                #pragma unroll
                for (int mf = 0; mf < 2; mf++) {
                    af[mf][0] = f2h2(sacc[mf][2 * kb][0],     sacc[mf][2 * kb][1]);
                    af[mf][1] = f2h2(sacc[mf][2 * kb][2],     sacc[mf][2 * kb][3]);
                    af[mf][2] = f2h2(sacc[mf][2 * kb + 1][0], sacc[mf][2 * kb + 1][1]);
                    af[mf][3] = f2h2(sacc[mf][2 * kb + 1][2], sacc[mf][2 * kb + 1][3]);
                }
                const int w0 = 32 * st + 8 * kb + tid;
                #pragma unroll
                for (int nb = 0; nb < 16; nb++) {
                    uint32_t b0 = smu[A8_KT + (8 * nb + g) * 68 + w0];
                    uint32_t b1 = smu[A8_KT + (8 * nb + g) * 68 + w0 + 4];
                    mma_f16(oacc[0][nb], af[0], b0, b1);
                    mma_f16(oacc[1][nb], af[1], b0, b1);
                }
            }
        }
    }

    #pragma unroll
    for (int mf = 0; mf < 2; mf++)
        #pragma unroll
        for (int hh = 0; hh < 2; hh++) {
            const int rl = rw0 + 16 * mf + g + 8 * hh;
            const float inv = 1.f / l_run[mf][hh];
            float* dst = ctx + qbase + (long)rl * 128;
            #pragma unroll
            for (int nb = 0; nb < 16; nb++)
                *(float2*)(dst + 8 * nb + 2 * tid) =
                    make_float2(oacc[mf][nb][2 * hh] * inv, oacc[mf][nb][2 * hh + 1] * inv);
        }
}

// ===========================================================================
extern "C" void kernel_launch(void* const* d_in, const int* in_sizes, int n_in,
                              void* d_out, int out_size)
{
    const float* x     = (const float*)d_in[0];
    const float* W_dq  = (const float*)d_in[1];
    const float* W_uq  = (const float*)d_in[2];
    const float* W_dkv = (const float*)d_in[3];
    const float* W_uk  = (const float*)d_in[4];
    const float* W_uv  = (const float*)d_in[5];
    const float* W_o   = (const float*)d_in[6];

    float* y   = (float*)d_out;
    float* ckv = y + (long)BT * Cc;

    float *P, *M, *Nt, *R, *Aq, *QLp, *CT;
    __half *KH, *KHT;
    cudaGetSymbolAddress((void**)&P,  g_P);
    cudaGetSymbolAddress((void**)&M,  g_M);
    cudaGetSymbolAddress((void**)&Nt, g_Nt);
    cudaGetSymbolAddress((void**)&R,  g_R);
    cudaGetSymbolAddress((void**)&Aq, g_Aq);
    cudaGetSymbolAddress((void**)&QLp, g_ql);
    cudaGetSymbolAddress((void**)&CT, g_ct);
    cudaGetSymbolAddress((void**)&KH,  g_kh);
    cudaGetSymbolAddress((void**)&KHT, g_khT);

    const int NONE = 1 << 30;
    const size_t S64   = 2 * (128 * 20 + 64 * 20) * 4;        // 30720
    const size_t S128  = 2 * (128 * 20 + 128 * 20) * 4;       // 40960
    const size_t S64C  = 2 * 2 * (128 * 20 + 64 * 20) * 4;    // 61440

    cudaFuncSetAttribute((const void*)hgemm<64, false, true, false>,
                         cudaFuncAttributeMaxDynamicSharedMemorySize, (int)S64C);
    cudaFuncSetAttribute((const void*)hgemm<128, false, false, true>,
                         cudaFuncAttributeMaxDynamicSharedMemorySize, (int)S128);
    cudaFuncSetAttribute((const void*)hgemm<64, true, false, false>,
                         cudaFuncAttributeMaxDynamicSharedMemorySize, (int)S64);
    cudaFuncSetAttribute((const void*)hgemm<64, false, false, false>,
                         cudaFuncAttributeMaxDynamicSharedMemorySize, (int)S64);

    // Exact fp32 precompute chain: P -> M -> Nt
    pk_kernel<<<128, 128>>>(W_uq, W_uk, P);
    m_kernel<<<1024, 128>>>(W_dq, P, M);
    n_kernel<<<dim3(128, 16), 128>>>(W_uq, M, Nt);

    // Fused x-GEMM (fp16 compensated), split-K=2
    {
        const long PS = (long)BT * 128;
        hgemm<64, false, true, false><<<dim3(32, 4, 2), 256, S64C>>>(
            x, W_dq, CT, W_dkv, CT + 2 * PS, 512,
            1024, 1024, 128, 512, 512, PS, 2, 1.f);
        reduce_add<<<512, 256>>>(CT,          Aq,  (int)(PS / 4), 2, PS / 4);
        reduce_add<<<512, 256>>>(CT + 2 * PS, ckv, (int)(PS / 4), 2, PS / 4);
    }

    // ckv -> fp16 (both layouts), one-shot
    cvt_kernel<<<dim3(16, 2), 256>>>(ckv, KH, KHT);

    // R = W_o @ W_uv (fp16 NN), split-K=4
    {
        const long PR = 1024 * 128;
        hgemm<64, true, false, false><<<dim3(8, 2, 4), 256, S64>>>(
            W_o, W_uv, CT, nullptr, nullptr, 256,
            1024, 128, 128, 256, 256 * 128, PR, NONE, 1.f);
        reduce_add<<<128, 256>>>(CT, R, (int)(PR / 4), 4, PR / 4);
    }

    // ql[h] = Aq @ N[h]  -> fp16, prescaled by 0.125*log2(e).
    // FIX (R13 bug): sC is applied to the float* base, so pass the half
    // head-stride divided by 2: BT*128 halves == BT*128/2 floats.
    hgemm<128, false, false, true><<<dim3(32, 1, 16), 256, S128>>>(
        Aq, Nt, QLp, nullptr, nullptr, 128, 128, 128, 128,
        0, 128 * 128, (long)BT * 128 / 2, NONE, QSCALE);

    // fp16 flash attention v8 -> ctx
    cudaFuncSetAttribute(attn8_kernel, cudaFuncAttributeMaxDynamicSharedMemorySize,
                         A8_WORDS * 4);
    attn8_kernel<<<dim3(16, 16, 2), 128, A8_WORDS * 4>>>(
        (const __half*)QLp, KH, KHT, CT);

    // y[:, h*64:] = ctx[h] @ R[h*64:, :]^T   (fp16, batched 16, K=128, N=64)
    hgemm<64, false, false, false><<<dim3(32, 1, 16), 256, S64>>>(
        CT, R, y, nullptr, nullptr, 128, 128, 128, 1024,
        (long)BT * 128, 64 * 128, 64, NONE, 1.f);
}

// round 15
// speedup vs baseline: 1.0662x; 1.0662x over previous
#include <cuda_runtime.h>
#include <cuda_fp16.h>
#include <cstdint>

// Problem constants (fixed by setup_inputs)
#define Bb    2
#define Tt    2048
#define Cc    1024
#define QLd   128
#define KVL   128
#define NHh   16
#define HSd   64
#define BT    (Bb*Tt)          // 4096

// Scratch (device globals: no allocation allowed)
__device__ float g_P [QLd*KVL];
__device__ float g_M [Cc*KVL];
__device__ float g_Nt[NHh*KVL*QLd];
__device__ float g_R [Cc*KVL];
__device__ float g_Aq[BT*QLd];
__device__ float g_ql[NHh*BT*KVL];       // holds fp16 latent queries (prescaled)
__device__ float g_ct[NHh*BT*KVL];       // latent context (also GEMM partial scratch)
__device__ __half g_kh [Bb*Tt*KVL];      // ckv fp16, s-major  [b][s][d]
__device__ __half g_khT[Bb*KVL*Tt];      // ckv fp16, d-major  [b][d][s]

#define QSCALE 0.18033688011112f         // 0.125 * log2(e)

__device__ __forceinline__ uint32_t f2h2(float a, float b) {
    __half2 h = __floats2half2_rn(a, b);
    return *(uint32_t*)&h;
}
__device__ __forceinline__ void mma_f16(float* d, const uint32_t* a, uint32_t b0, uint32_t b1) {
    asm volatile(
        "mma.sync.aligned.m16n8k16.row.col.f32.f16.f16.f32 "
        "{%0,%1,%2,%3}, {%4,%5,%6,%7}, {%8,%9}, {%0,%1,%2,%3};"
        : "+f"(d[0]), "+f"(d[1]), "+f"(d[2]), "+f"(d[3])
        : "r"(a[0]), "r"(a[1]), "r"(a[2]), "r"(a[3]), "r"(b0), "r"(b1));
}

// ===========================================================================
// fp16 tensor-core GEMM, software-pipelined, double-buffered (R12 + HOUT).
// HOUT: epilogue scales by oscale and stores __half; batching callers pass
// sC in FLOAT units (half-stride / 2) because the z-advance is on float*.
// ===========================================================================
template<int BN, bool NN, bool COMP, bool HOUT>
__global__ __launch_bounds__(256)
void hgemm(const float* __restrict__ A, const float* __restrict__ B,
           float* __restrict__ C, const float* __restrict__ B2,
           float* __restrict__ C2, int K,
           int lda, int ldb, int ldc, long sA, long sB, long sC, int nb1,
           float oscale)
{
    constexpr int BM = 128, AW = BM * 20, BW = BN * 20;
    constexpr int NF = BN / 16;
    constexpr int STG = (COMP ? 2 : 1) * (AW + BW);
    constexpr int NA4 = BM * 8 / 256;
    constexpr int NB4 = BN * 8 / 256;
    extern __shared__ uint32_t sh[];

    const int z = blockIdx.z;
    A += (long)z * sA;
    const float* Bp = B;  float* Cp = C;
    int by = blockIdx.y;
    if (by >= nb1) { Bp = B2; Cp = C2; by -= nb1; }
    Bp += (long)z * sB;  Cp += (long)z * sC;

    const int m0 = blockIdx.x * BM, n0 = by * BN;
    const int t = threadIdx.x;
    const int wid = t >> 5, g = (t & 31) >> 2, tid = t & 3;
    const int wm = wid >> 1, wn = wid & 1;

    float accH[2][NF][4];
    float accL[COMP ? 2 : 1][COMP ? NF : 1][4];
    #pragma unroll
    for (int i = 0; i < 2; i++)
        #pragma unroll
        for (int j = 0; j < NF; j++)
            #pragma unroll
            for (int q = 0; q < 4; q++) {
                accH[i][j][q] = 0.f;
                if (COMP) accL[i][j][q] = 0.f;
            }

    float4 aR[NA4], bR[NB4];

    auto loadTile = [&](int k0) {
        #pragma unroll
        for (int i = 0; i < NA4; i++) {
            int idx = t + i * 256;
            int r = idx >> 3, c4 = (idx & 7) * 4;
            aR[i] = *(const float4*)(A + (long)(m0 + r) * lda + k0 + c4);
        }
        if (!NN) {
            #pragma unroll
            for (int i = 0; i < NB4; i++) {
                int idx = t + i * 256;
                int r = idx >> 3, c4 = (idx & 7) * 4;
                bR[i] = *(const float4*)(Bp + (long)(n0 + r) * ldb + k0 + c4);
            }
        } else {
            #pragma unroll
            for (int i = 0; i < NB4; i++) {
                int idx = t + i * 256;
                int kr = idx / (BN / 4);
                int nn = (idx % (BN / 4)) * 4;
                bR[i] = *(const float4*)(Bp + (long)(k0 + kr) * ldb + n0 + nn);
            }
        }
    };
    auto storeTile = [&](int s) {
        uint32_t* Ah = sh + s * STG;
        uint32_t* Bh = Ah + AW;
        uint32_t* Al = Bh + BW;
        uint32_t* Bl = Al + AW;
        #pragma unroll
        for (int i = 0; i < NA4; i++) {
            int idx = t + i * 256;
            int r = idx >> 3, c4 = (idx & 7) * 4;
            float4 v = aR[i];
            uint32_t h0 = f2h2(v.x, v.y), h1 = f2h2(v.z, v.w);
            Ah[r * 20 + (c4 >> 1)]     = h0;
            Ah[r * 20 + (c4 >> 1) + 1] = h1;
            if (COMP) {
                __half2 p0 = *(__half2*)&h0, p1 = *(__half2*)&h1;
                float2 f0 = __half22float2(p0), f1 = __half22float2(p1);
                Al[r * 20 + (c4 >> 1)]     = f2h2((v.x - f0.x) * 1024.f, (v.y - f0.y) * 1024.f);
                Al[r * 20 + (c4 >> 1) + 1] = f2h2((v.z - f1.x) * 1024.f, (v.w - f1.y) * 1024.f);
            }
        }
        if (!NN) {
            #pragma unroll
            for (int i = 0; i < NB4; i++) {
                int idx = t + i * 256;
                int r = idx >> 3, c4 = (idx & 7) * 4;
                float4 v = bR[i];
                uint32_t h0 = f2h2(v.x, v.y), h1 = f2h2(v.z, v.w);
                Bh[r * 20 + (c4 >> 1)]     = h0;
                Bh[r * 20 + (c4 >> 1) + 1] = h1;
                if (COMP) {
                    __half2 p0 = *(__half2*)&h0, p1 = *(__half2*)&h1;
                    float2 f0 = __half22float2(p0), f1 = __half22float2(p1);
                    Bl[r * 20 + (c4 >> 1)]     = f2h2((v.x - f0.x) * 1024.f, (v.y - f0.y) * 1024.f);
                    Bl[r * 20 + (c4 >> 1) + 1] = f2h2((v.z - f1.x) * 1024.f, (v.w - f1.y) * 1024.f);
                }
            }
        } else {
            __half* Bhh = (__half*)Bh;
            #pragma unroll
            for (int i = 0; i < NB4; i++) {
                int idx = t + i * 256;
                int kr = idx / (BN / 4);
                int nn = (idx % (BN / 4)) * 4;
                float4 v = bR[i];
                Bhh[(nn + 0) * 40 + kr] = __float2half_rn(v.x);
                Bhh[(nn + 1) * 40 + kr] = __float2half_rn(v.y);
                Bhh[(nn + 2) * 40 + kr] = __float2half_rn(v.z);
                Bhh[(nn + 3) * 40 + kr] = __float2half_rn(v.w);
            }
        }
    };

    const int nk = K / 32;
    loadTile(0);
    storeTile(0);
    __syncthreads();

    for (int it = 0; it < nk; it++) {
        if (it + 1 < nk) loadTile(32 * (it + 1));

        const uint32_t* Ah = sh + (it & 1) * STG;
        const uint32_t* Bh = Ah + AW;
        const uint32_t* Al = Bh + BW;
        const uint32_t* Bl = Al + AW;

        #pragma unroll
        for (int s = 0; s < 2; s++) {
            const int kk = 8 * s + tid;
            uint32_t ah[2][4], al[2][4];
            #pragma unroll
            for (int mf = 0; mf < 2; mf++) {
                int r = wm * 32 + 16 * mf + g;
                ah[mf][0] = Ah[r * 20 + kk];       ah[mf][1] = Ah[(r + 8) * 20 + kk];
                ah[mf][2] = Ah[r * 20 + kk + 4];   ah[mf][3] = Ah[(r + 8) * 20 + kk + 4];
                if (COMP) {
                    al[mf][0] = Al[r * 20 + kk];     al[mf][1] = Al[(r + 8) * 20 + kk];
                    al[mf][2] = Al[r * 20 + kk + 4]; al[mf][3] = Al[(r + 8) * 20 + kk + 4];
                }
            }
            #pragma unroll
            for (int nf = 0; nf < NF; nf++) {
                int n = wn * (BN / 2) + 8 * nf + g;
                uint32_t b0 = Bh[n * 20 + kk], b1 = Bh[n * 20 + kk + 4];
                #pragma unroll
                for (int mf = 0; mf < 2; mf++) {
                    mma_f16(accH[mf][nf], ah[mf], b0, b1);
                    if (COMP) mma_f16(accL[mf][nf], al[mf], b0, b1);
                }
                if (COMP) {
                    uint32_t c0 = Bl[n * 20 + kk], c1 = Bl[n * 20 + kk + 4];
                    #pragma unroll
                    for (int mf = 0; mf < 2; mf++)
                        mma_f16(accL[mf][nf], ah[mf], c0, c1);
                }
            }
        }

        if (it + 1 < nk) storeTile((it + 1) & 1);
        __syncthreads();
    }

    const float lsc = 1.f / 1024.f;
    #pragma unroll
    for (int mf = 0; mf < 2; mf++) {
        const int r0 = m0 + wm * 32 + 16 * mf + g;
        #pragma unroll
        for (int nf = 0; nf < NF; nf++) {
            const int c = n0 + wn * (BN / 2) + 8 * nf + 2 * tid;
            float v0 = accH[mf][nf][0], v1 = accH[mf][nf][1];
            float v2 = accH[mf][nf][2], v3 = accH[mf][nf][3];
            if (COMP) {
                v0 += accL[mf][nf][0] * lsc;  v1 += accL[mf][nf][1] * lsc;
                v2 += accL[mf][nf][2] * lsc;  v3 += accL[mf][nf][3] * lsc;
            }
            if (HOUT) {
                __half* Ch = (__half*)Cp;
                __half2 h0 = __floats2half2_rn(v0 * oscale, v1 * oscale);
                __half2 h1 = __floats2half2_rn(v2 * oscale, v3 * oscale);
                *(__half2*)(Ch + (long)r0 * ldc + c)       = h0;
                *(__half2*)(Ch + (long)(r0 + 8) * ldc + c) = h1;
            } else {
                *(float2*)(Cp + (long)r0 * ldc + c)       = make_float2(v0, v1);
                *(float2*)(Cp + (long)(r0 + 8) * ldc + c) = make_float2(v2, v3);
            }
        }
    }
}

// Split-K partial reduction (float4-wide)
__global__ __launch_bounds__(256)
void reduce_add(const float* __restrict__ src, float* __restrict__ dst,
                int n4, int parts, long pstride4)
{
    int i = blockIdx.x * blockDim.x + threadIdx.x;
    if (i >= n4) return;
    const float4* s = (const float4*)src;
    float4 acc = s[i];
    for (int p = 1; p < parts; p++) {
        float4 v = s[i + (long)p * pstride4];
        acc.x += v.x; acc.y += v.y; acc.z += v.z; acc.w += v.w;
    }
    ((float4*)dst)[i] = acc;
}

// ===========================================================================
// ckv -> fp16 one-shot conversion, both layouts (unchanged)
// ===========================================================================
__global__ __launch_bounds__(256)
void cvt_kernel(const float* __restrict__ ckv, __half* __restrict__ kh,
                __half* __restrict__ khT)
{
    __shared__ __half sm[128 * 132];
    const int st = blockIdx.x, b = blockIdx.y;
    const float* src = ckv + ((long)b * Tt + st * 128) * 128;
    __half* dsh = kh + ((long)b * Tt + st * 128) * 128;
    const int t = threadIdx.x;

    #pragma unroll
    for (int i = 0; i < 16; i++) {
        int idx = t + i * 256;
        int r = idx >> 5, c = (idx & 31) * 4;
        float4 v = *(const float4*)(src + (long)r * 128 + c);
        uint2 u = make_uint2(f2h2(v.x, v.y), f2h2(v.z, v.w));
        *(uint2*)(dsh + (long)r * 128 + c) = u;
        *(uint2*)(sm + r * 132 + c) = u;
    }
    __syncthreads();

    #pragma unroll
    for (int i = 0; i < 16; i++) {
        int idx = t + i * 256;
        int d = idx >> 5, sg = (idx & 31) * 4;
        __half h0 = sm[(sg + 0) * 132 + d];
        __half h1 = sm[(sg + 1) * 132 + d];
        __half h2 = sm[(sg + 2) * 132 + d];
        __half h3 = sm[(sg + 3) * 132 + d];
        uint2 u;
        __half2 p0 = __halves2half2(h0, h1);
        __half2 p1 = __halves2half2(h2, h3);
        u.x = *(uint32_t*)&p0;  u.y = *(uint32_t*)&p1;
        *(uint2*)(khT + ((long)b * 128 + d) * Tt + st * 128 + sg) = u;
    }
}

// ===========================================================================
// Tiny fp32-exact precompute kernels (unchanged)
// ===========================================================================
__global__ __launch_bounds__(128)
void pk_kernel(const float* __restrict__ W_uq, const float* __restrict__ W_uk,
               float* __restrict__ P)
{
    const int i = blockIdx.x, j = threadIdx.x;
    float s = 0.f;
    #pragma unroll 8
    for (int c = 0; c < 1024; c++)
        s += W_uq[c * 128 + i] * W_uk[c * 128 + j];
    P[i * 128 + j] = s;
}
__global__ __launch_bounds__(128)
void m_kernel(const float* __restrict__ W_dq, const float* __restrict__ P,
              float* __restrict__ M)
{
    const int c = blockIdx.x, j = threadIdx.x;
    float s = 0.f;
    #pragma unroll 8
    for (int i = 0; i < 128; i++)
        s += W_dq[i * 1024 + c] * P[i * 128 + j];
    M[c * 128 + j] = s;
}
__global__ __launch_bounds__(128)
void n_kernel(const float* __restrict__ W_uq, const float* __restrict__ M,
              float* __restrict__ Nt)
{
    const int j = blockIdx.x, h = blockIdx.y, i = threadIdx.x;
    float s = 0.f;
    #pragma unroll 8
    for (int d = 0; d < 64; d++)
        s += W_uq[(h * 64 + d) * 128 + i] * M[(h * 64 + d) * 128 + j];
    Nt[(h * 128 + j) * 128 + i] = s;
}

// ===========================================================================
// fp16 mma flash attention v9 = proven attn7 (R12, 309 us) consuming the
// fp16 prescaled ql directly (Q frags = plain uint32 gmem reads, no cvt)
// and exp2-domain softmax (scale folded into QSCALE upstream).
// 64 q x 128-key tiles, register-resident P, K1/KT fp16 smem tiles (stride
// 68 words, conflict-free), 69.6 KB smem, 128 thr, 2 CTAs/SM.
// ===========================================================================
#define A7_K1 0
#define A7_KT (128 * 68)
#define A7_WORDS (2 * 128 * 68)        // 69632 B

__global__ __launch_bounds__(128, 2)
void attn9_kernel(const __half* __restrict__ qlh, const __half* __restrict__ khG,
                  const __half* __restrict__ khTG, float* __restrict__ ctx)
{
    extern __shared__ uint32_t smu[];
    const int t = threadIdx.x;
    const int w = t >> 5, lid = t & 31;
    const int g = lid >> 2, tid = lid & 3;

    const int h  = blockIdx.x;               // fastest: K-tile L2 sharing
    const int qt = 31 - blockIdx.y;          // heavy q-tiles first
    const int b  = blockIdx.z;
    const long qbase = ((long)h * BT + (long)b * Tt + (long)qt * 64) * 128;

    const int rl0 = 16 * w + g;              // local query row (0..63)
    const int nkt = (qt >> 1) + 1;           // 128-key tiles

    // ---- Q A-fragments: direct fp16 loads (prescaled upstream) ----
    uint32_t qf[8][4];
    {
        const __half* qr0 = qlh + qbase + (long)rl0 * 128;
        const __half* qr1 = qr0 + 8 * 128;
        #pragma unroll
        for (int kb = 0; kb < 8; kb++) {
            const int c = 16 * kb + 2 * tid;
            qf[kb][0] = *(const uint32_t*)(qr0 + c);
            qf[kb][1] = *(const uint32_t*)(qr1 + c);
            qf[kb][2] = *(const uint32_t*)(qr0 + c + 8);
            qf[kb][3] = *(const uint32_t*)(qr1 + c + 8);
        }
    }

    float oacc[16][4];
    #pragma unroll
    for (int nb = 0; nb < 16; nb++)
        #pragma unroll
        for (int q = 0; q < 4; q++) oacc[nb][q] = 0.f;

    float m_run[2] = { -1e30f, -1e30f };
    float l_run[2] = { 0.f, 0.f };

    for (int kt = 0; kt < nkt; kt++) {
        __syncthreads();
        {
            const __half* kh  = khG  + ((long)b * Tt + (long)kt * 128) * 128;
            const __half* khT = khTG + (long)b * 128 * Tt + (long)kt * 128;
            #pragma unroll
            for (int i = 0; i < 16; i++) {
                int idx = t + i * 128;
                int r = idx >> 4, c = idx & 15;
                *(uint4*)(smu + A7_K1 + r * 68 + c * 4) =
                    *(const uint4*)(kh + (long)r * 128 + c * 8);
            }
            #pragma unroll
            for (int i = 0; i < 16; i++) {
                int idx = t + i * 128;
                int d = idx >> 4, c = idx & 15;
                *(uint4*)(smu + A7_KT + d * 68 + c * 4) =
                    *(const uint4*)(khT + (long)d * Tt + c * 8);
            }
        }
        __syncthreads();

        // ---- S = Q K^T ----
        float sacc[16][4];
        #pragma unroll
        for (int nb = 0; nb < 16; nb++)
            #pragma unroll
            for (int q = 0; q < 4; q++) sacc[nb][q] = 0.f;

        #pragma unroll
        for (int kb = 0; kb < 8; kb++) {
            const int w0 = 8 * kb + tid;
            #pragma unroll
            for (int nb = 0; nb < 16; nb++) {
                uint32_t b0 = smu[A7_K1 + (8 * nb + g) * 68 + w0];
                uint32_t b1 = smu[A7_K1 + (8 * nb + g) * 68 + w0 + 4];
                mma_f16(sacc[nb], qf[kb], b0, b1);
            }
        }

        // ---- causal mask (last tile only) ----
        if (kt == nkt - 1) {
            const int row0 = 64 * qt + rl0;
            #pragma unroll
            for (int nb = 0; nb < 16; nb++)
                #pragma unroll
                for (int j = 0; j < 2; j++) {
                    const int col = 128 * kt + 8 * nb + 2 * tid + j;
                    if (col > row0)     sacc[nb][j]     = -1e30f;
                    if (col > row0 + 8) sacc[nb][2 + j] = -1e30f;
                }
        }

        // ---- online softmax (exp2 domain); P stays in sacc registers ----
        #pragma unroll
        for (int hh = 0; hh < 2; hh++) {
            float mt = -1e30f;
            #pragma unroll
            for (int nb = 0; nb < 16; nb++)
                mt = fmaxf(mt, fmaxf(sacc[nb][2 * hh], sacc[nb][2 * hh + 1]));
            mt = fmaxf(mt, __shfl_xor_sync(0xffffffffu, mt, 1));
            mt = fmaxf(mt, __shfl_xor_sync(0xffffffffu, mt, 2));

            const float mn = fmaxf(m_run[hh], mt);
            const float sc = exp2f(m_run[hh] - mn);
            float ls = 0.f;
            #pragma unroll
            for (int nb = 0; nb < 16; nb++) {
                float p0 = exp2f(sacc[nb][2 * hh]     - mn);
                float p1 = exp2f(sacc[nb][2 * hh + 1] - mn);
                ls += p0 + p1;
                sacc[nb][2 * hh]     = p0;
                sacc[nb][2 * hh + 1] = p1;
            }
            ls += __shfl_xor_sync(0xffffffffu, ls, 1);
            ls += __shfl_xor_sync(0xffffffffu, ls, 2);
            l_run[hh] = l_run[hh] * sc + ls;
            m_run[hh] = mn;
            #pragma unroll
            for (int nb = 0; nb < 16; nb++) {
                oacc[nb][2 * hh]     *= sc;
                oacc[nb][2 * hh + 1] *= sc;
            }
        }

        // ---- O += P @ Ktile : P packed from sacc (register-resident) ----
        #pragma unroll
        for (int kb = 0; kb < 8; kb++) {
            uint32_t af[4];
            af[0] = f2h2(sacc[2 * kb][0],     sacc[2 * kb][1]);
            af[1] = f2h2(sacc[2 * kb][2],     sacc[2 * kb][3]);
            af[2] = f2h2(sacc[2 * kb + 1][0], sacc[2 * kb + 1][1]);
            af[3] = f2h2(sacc[2 * kb + 1][2], sacc[2 * kb + 1][3]);
            const int w0 = 8 * kb + tid;
            #pragma unroll
            for (int nb = 0; nb < 16; nb++) {
                uint32_t b0 = smu[A7_KT + (8 * nb + g) * 68 + w0];
                uint32_t b1 = smu[A7_KT + (8 * nb + g) * 68 + w0 + 4];
                mma_f16(oacc[nb], af, b0, b1);
            }
        }
    }

    // ---- epilogue: ctx = O / l ----
    #pragma unroll
    for (int hh = 0; hh < 2; hh++) {
        const int rl = rl0 + 8 * hh;
        const float inv = 1.f / l_run[hh];
        float* dst = ctx + qbase + (long)rl * 128;
        #pragma unroll
        for (int nb = 0; nb < 16; nb++)
            *(float2*)(dst + 8 * nb + 2 * tid) =
                make_float2(oacc[nb][2 * hh] * inv, oacc[nb][2 * hh + 1] * inv);
    }
}

// ===========================================================================
extern "C" void kernel_launch(void* const* d_in, const int* in_sizes, int n_in,
                              void* d_out, int out_size)
{
    const float* x     = (const float*)d_in[0];
    const float* W_dq  = (const float*)d_in[1];
    const float* W_uq  = (const float*)d_in[2];
    const float* W_dkv = (const float*)d_in[3];
    const float* W_uk  = (const float*)d_in[4];
    const float* W_uv  = (const float*)d_in[5];
    const float* W_o   = (const float*)d_in[6];

    float* y   = (float*)d_out;
    float* ckv = y + (long)BT * Cc;

    float *P, *M, *Nt, *R, *Aq, *QLp, *CT;
    __half *KH, *KHT;
    cudaGetSymbolAddress((void**)&P,  g_P);
    cudaGetSymbolAddress((void**)&M,  g_M);
    cudaGetSymbolAddress((void**)&Nt, g_Nt);
    cudaGetSymbolAddress((void**)&R,  g_R);
    cudaGetSymbolAddress((void**)&Aq, g_Aq);
    cudaGetSymbolAddress((void**)&QLp, g_ql);
    cudaGetSymbolAddress((void**)&CT, g_ct);
    cudaGetSymbolAddress((void**)&KH,  g_kh);
    cudaGetSymbolAddress((void**)&KHT, g_khT);

    const int NONE = 1 << 30;
    const size_t S64   = 2 * (128 * 20 + 64 * 20) * 4;        // 30720
    const size_t S128  = 2 * (128 * 20 + 128 * 20) * 4;       // 40960
    const size_t S64C  = 2 * 2 * (128 * 20 + 64 * 20) * 4;    // 61440

    cudaFuncSetAttribute((const void*)hgemm<64, false, true, false>,
                         cudaFuncAttributeMaxDynamicSharedMemorySize, (int)S64C);
    cudaFuncSetAttribute((const void*)hgemm<128, false, false, true>,
                         cudaFuncAttributeMaxDynamicSharedMemorySize, (int)S128);
    cudaFuncSetAttribute((const void*)hgemm<64, true, false, false>,
                         cudaFuncAttributeMaxDynamicSharedMemorySize, (int)S64);
    cudaFuncSetAttribute((const void*)hgemm<64, false, false, false>,
                         cudaFuncAttributeMaxDynamicSharedMemorySize, (int)S64);

    // Exact fp32 precompute chain: P -> M -> Nt
    pk_kernel<<<128, 128>>>(W_uq, W_uk, P);
    m_kernel<<<1024, 128>>>(W_dq, P, M);
    n_kernel<<<dim3(128, 16), 128>>>(W_uq, M, Nt);

    // Fused x-GEMM (fp16 compensated), split-K=2
    {
        const long PS = (long)BT * 128;
        hgemm<64, false, true, false><<<dim3(32, 4, 2), 256, S64C>>>(
            x, W_dq, CT, W_dkv, CT + 2 * PS, 512,
            1024, 1024, 128, 512, 512, PS, 2, 1.f);
        reduce_add<<<512, 256>>>(CT,          Aq,  (int)(PS / 4), 2, PS / 4);
        reduce_add<<<512, 256>>>(CT + 2 * PS, ckv, (int)(PS / 4), 2, PS / 4);
    }

    // ckv -> fp16 (both layouts), one-shot
    cvt_kernel<<<dim3(16, 2), 256>>>(ckv, KH, KHT);

    // R = W_o @ W_uv (fp16 NN), split-K=4
    {
        const long PR = 1024 * 128;
        hgemm<64, true, false, false><<<dim3(8, 2, 4), 256, S64>>>(
            W_o, W_uv, CT, nullptr, nullptr, 256,
            1024, 128, 128, 256, 256 * 128, PR, NONE, 1.f);
        reduce_add<<<128, 256>>>(CT, R, (int)(PR / 4), 4, PR / 4);
    }

    // ql[h] = Aq @ N[h] -> fp16, prescaled by 0.125*log2(e)
    // (sC in FLOAT units: BT*128 halves == BT*128/2 floats)
    hgemm<128, false, false, true><<<dim3(32, 1, 16), 256, S128>>>(
        Aq, Nt, QLp, nullptr, nullptr, 128, 128, 128, 128,
        0, 128 * 128, (long)BT * 128 / 2, NONE, QSCALE);

    // fp16 flash attention v9 -> ctx
    cudaFuncSetAttribute(attn9_kernel, cudaFuncAttributeMaxDynamicSharedMemorySize,
                         A7_WORDS * 4);
    attn9_kernel<<<dim3(16, 32, 2), 128, A7_WORDS * 4>>>(
        (const __half*)QLp, KH, KHT, CT);

    // y[:, h*64:] = ctx[h] @ R[h*64:, :]^T   (fp16, batched 16, K=128, N=64)
    hgemm<64, false, false, false><<<dim3(32, 1, 16), 256, S64>>>(
        CT, R, y, nullptr, nullptr, 128, 128, 128, 1024,
        (long)BT * 128, 64 * 128, 64, NONE, 1.f);
}

// round 17
// speedup vs baseline: 1.1747x; 1.1017x over previous
#include <cuda_runtime.h>
#include <cuda_fp16.h>
#include <cstdint>

// Problem constants (fixed by setup_inputs)
#define Bb    2
#define Tt    2048
#define Cc    1024
#define QLd   128
#define KVL   128
#define NHh   16
#define HSd   64
#define BT    (Bb*Tt)          // 4096

// Scratch (device globals: no allocation allowed)
__device__ float g_P [QLd*KVL];
__device__ float g_M [Cc*KVL];
__device__ float g_Nt[NHh*KVL*QLd];
__device__ float g_R [Cc*KVL];
__device__ float g_Aq[BT*QLd];
__device__ float g_ql[NHh*BT*KVL];       // holds fp16 latent queries (prescaled)
__device__ float g_ct[NHh*BT*KVL];       // latent context (also GEMM partial scratch)
__device__ __half g_kh [Bb*Tt*KVL];      // ckv fp16, s-major  [b][s][d]

#define QSCALE 0.18033688011112f         // 0.125 * log2(e)

__device__ __forceinline__ uint32_t f2h2(float a, float b) {
    __half2 h = __floats2half2_rn(a, b);
    return *(uint32_t*)&h;
}
__device__ __forceinline__ uint32_t smem_u32(const void* p) {
    uint32_t a;
    asm("{ .reg .u64 t; cvta.to.shared.u64 t, %1; cvt.u32.u64 %0, t; }" : "=r"(a) : "l"(p));
    return a;
}
__device__ __forceinline__ void mma_f16(float* d, const uint32_t* a, uint32_t b0, uint32_t b1) {
    asm volatile(
        "mma.sync.aligned.m16n8k16.row.col.f32.f16.f16.f32 "
        "{%0,%1,%2,%3}, {%4,%5,%6,%7}, {%8,%9}, {%0,%1,%2,%3};"
        : "+f"(d[0]), "+f"(d[1]), "+f"(d[2]), "+f"(d[3])
        : "r"(a[0]), "r"(a[1]), "r"(a[2]), "r"(a[3]), "r"(b0), "r"(b1));
}
__device__ __forceinline__ void ldsm4t(uint32_t* r, uint32_t saddr) {
    asm volatile("ldmatrix.sync.aligned.m8n8.x4.trans.shared.b16 {%0,%1,%2,%3}, [%4];"
        : "=r"(r[0]), "=r"(r[1]), "=r"(r[2]), "=r"(r[3]) : "r"(saddr));
}

// ===========================================================================
// fp16 tensor-core GEMM, software-pipelined, double-buffered (unchanged R15)
// ===========================================================================
template<int BN, bool NN, bool COMP, bool HOUT>
__global__ __launch_bounds__(256)
void hgemm(const float* __restrict__ A, const float* __restrict__ B,
           float* __restrict__ C, const float* __restrict__ B2,
           float* __restrict__ C2, int K,
           int lda, int ldb, int ldc, long sA, long sB, long sC, int nb1,
           float oscale)
{
    constexpr int BM = 128, AW = BM * 20, BW = BN * 20;
    constexpr int NF = BN / 16;
    constexpr int STG = (COMP ? 2 : 1) * (AW + BW);
    constexpr int NA4 = BM * 8 / 256;
    constexpr int NB4 = BN * 8 / 256;
    extern __shared__ uint32_t sh[];

    const int z = blockIdx.z;
    A += (long)z * sA;
    const float* Bp = B;  float* Cp = C;
    int by = blockIdx.y;
    if (by >= nb1) { Bp = B2; Cp = C2; by -= nb1; }
    Bp += (long)z * sB;  Cp += (long)z * sC;

    const int m0 = blockIdx.x * BM, n0 = by * BN;
    const int t = threadIdx.x;
    const int wid = t >> 5, g = (t & 31) >> 2, tid = t & 3;
    const int wm = wid >> 1, wn = wid & 1;

    float accH[2][NF][4];
    float accL[COMP ? 2 : 1][COMP ? NF : 1][4];
    #pragma unroll
    for (int i = 0; i < 2; i++)
        #pragma unroll
        for (int j = 0; j < NF; j++)
            #pragma unroll
            for (int q = 0; q < 4; q++) {
                accH[i][j][q] = 0.f;
                if (COMP) accL[i][j][q] = 0.f;
            }

    float4 aR[NA4], bR[NB4];

    auto loadTile = [&](int k0) {
        #pragma unroll
        for (int i = 0; i < NA4; i++) {
            int idx = t + i * 256;
            int r = idx >> 3, c4 = (idx & 7) * 4;
            aR[i] = *(const float4*)(A + (long)(m0 + r) * lda + k0 + c4);
        }
        if (!NN) {
            #pragma unroll
            for (int i = 0; i < NB4; i++) {
                int idx = t + i * 256;
                int r = idx >> 3, c4 = (idx & 7) * 4;
                bR[i] = *(const float4*)(Bp + (long)(n0 + r) * ldb + k0 + c4);
            }
        } else {
            #pragma unroll
            for (int i = 0; i < NB4; i++) {
                int idx = t + i * 256;
                int kr = idx / (BN / 4);
                int nn = (idx % (BN / 4)) * 4;
                bR[i] = *(const float4*)(Bp + (long)(k0 + kr) * ldb + n0 + nn);
            }
        }
    };
    auto storeTile = [&](int s) {
        uint32_t* Ah = sh + s * STG;
        uint32_t* Bh = Ah + AW;
        uint32_t* Al = Bh + BW;
        uint32_t* Bl = Al + AW;
        #pragma unroll
        for (int i = 0; i < NA4; i++) {
            int idx = t + i * 256;
            int r = idx >> 3, c4 = (idx & 7) * 4;
            float4 v = aR[i];
            uint32_t h0 = f2h2(v.x, v.y), h1 = f2h2(v.z, v.w);
            Ah[r * 20 + (c4 >> 1)]     = h0;
            Ah[r * 20 + (c4 >> 1) + 1] = h1;
            if (COMP) {
                __half2 p0 = *(__half2*)&h0, p1 = *(__half2*)&h1;
                float2 f0 = __half22float2(p0), f1 = __half22float2(p1);
                Al[r * 20 + (c4 >> 1)]     = f2h2((v.x - f0.x) * 1024.f, (v.y - f0.y) * 1024.f);
                Al[r * 20 + (c4 >> 1) + 1] = f2h2((v.z - f1.x) * 1024.f, (v.w - f1.y) * 1024.f);
            }
        }
        if (!NN) {
            #pragma unroll
            for (int i = 0; i < NB4; i++) {
                int idx = t + i * 256;
                int r = idx >> 3, c4 = (idx & 7) * 4;
                float4 v = bR[i];
                uint32_t h0 = f2h2(v.x, v.y), h1 = f2h2(v.z, v.w);
                Bh[r * 20 + (c4 >> 1)]     = h0;
                Bh[r * 20 + (c4 >> 1) + 1] = h1;
                if (COMP) {
                    __half2 p0 = *(__half2*)&h0, p1 = *(__half2*)&h1;
                    float2 f0 = __half22float2(p0), f1 = __half22float2(p1);
                    Bl[r * 20 + (c4 >> 1)]     = f2h2((v.x - f0.x) * 1024.f, (v.y - f0.y) * 1024.f);
                    Bl[r * 20 + (c4 >> 1) + 1] = f2h2((v.z - f1.x) * 1024.f, (v.w - f1.y) * 1024.f);
                }
            }
        } else {
            __half* Bhh = (__half*)Bh;
            #pragma unroll
            for (int i = 0; i < NB4; i++) {
                int idx = t + i * 256;
                int kr = idx / (BN / 4);
                int nn = (idx % (BN / 4)) * 4;
                float4 v = bR[i];
                Bhh[(nn + 0) * 40 + kr] = __float2half_rn(v.x);
                Bhh[(nn + 1) * 40 + kr] = __float2half_rn(v.y);
                Bhh[(nn + 2) * 40 + kr] = __float2half_rn(v.z);
                Bhh[(nn + 3) * 40 + kr] = __float2half_rn(v.w);
            }
        }
    };

    const int nk = K / 32;
    loadTile(0);
    storeTile(0);
    __syncthreads();

    for (int it = 0; it < nk; it++) {
        if (it + 1 < nk) loadTile(32 * (it + 1));

        const uint32_t* Ah = sh + (it & 1) * STG;
        const uint32_t* Bh = Ah + AW;
        const uint32_t* Al = Bh + BW;
        const uint32_t* Bl = Al + AW;

        #pragma unroll
        for (int s = 0; s < 2; s++) {
            const int kk = 8 * s + tid;
            uint32_t ah[2][4], al[2][4];
            #pragma unroll
            for (int mf = 0; mf < 2; mf++) {
                int r = wm * 32 + 16 * mf + g;
                ah[mf][0] = Ah[r * 20 + kk];       ah[mf][1] = Ah[(r + 8) * 20 + kk];
                ah[mf][2] = Ah[r * 20 + kk + 4];   ah[mf][3] = Ah[(r + 8) * 20 + kk + 4];
                if (COMP) {
                    al[mf][0] = Al[r * 20 + kk];     al[mf][1] = Al[(r + 8) * 20 + kk];
                    al[mf][2] = Al[r * 20 + kk + 4]; al[mf][3] = Al[(r + 8) * 20 + kk + 4];
                }
            }
            #pragma unroll
            for (int nf = 0; nf < NF; nf++) {
                int n = wn * (BN / 2) + 8 * nf + g;
                uint32_t b0 = Bh[n * 20 + kk], b1 = Bh[n * 20 + kk + 4];
                #pragma unroll
                for (int mf = 0; mf < 2; mf++) {
                    mma_f16(accH[mf][nf], ah[mf], b0, b1);
                    if (COMP) mma_f16(accL[mf][nf], al[mf], b0, b1);
                }
                if (COMP) {
                    uint32_t c0 = Bl[n * 20 + kk], c1 = Bl[n * 20 + kk + 4];
                    #pragma unroll
                    for (int mf = 0; mf < 2; mf++)
                        mma_f16(accL[mf][nf], ah[mf], c0, c1);
                }
            }
        }

        if (it + 1 < nk) storeTile((it + 1) & 1);
        __syncthreads();
    }

    const float lsc = 1.f / 1024.f;
    #pragma unroll
    for (int mf = 0; mf < 2; mf++) {
        const int r0 = m0 + wm * 32 + 16 * mf + g;
        #pragma unroll
        for (int nf = 0; nf < NF; nf++) {
            const int c = n0 + wn * (BN / 2) + 8 * nf + 2 * tid;
            float v0 = accH[mf][nf][0], v1 = accH[mf][nf][1];
            float v2 = accH[mf][nf][2], v3 = accH[mf][nf][3];
            if (COMP) {
                v0 += accL[mf][nf][0] * lsc;  v1 += accL[mf][nf][1] * lsc;
                v2 += accL[mf][nf][2] * lsc;  v3 += accL[mf][nf][3] * lsc;
            }
            if (HOUT) {
                __half* Ch = (__half*)Cp;
                __half2 h0 = __floats2half2_rn(v0 * oscale, v1 * oscale);
                __half2 h1 = __floats2half2_rn(v2 * oscale, v3 * oscale);
                *(__half2*)(Ch + (long)r0 * ldc + c)       = h0;
                *(__half2*)(Ch + (long)(r0 + 8) * ldc + c) = h1;
            } else {
                *(float2*)(Cp + (long)r0 * ldc + c)       = make_float2(v0, v1);
                *(float2*)(Cp + (long)(r0 + 8) * ldc + c) = make_float2(v2, v3);
            }
        }
    }
}

// Split-K partial reduction (float4-wide)
__global__ __launch_bounds__(256)
void reduce_add(const float* __restrict__ src, float* __restrict__ dst,
                int n4, int parts, long pstride4)
{
    int i = blockIdx.x * blockDim.x + threadIdx.x;
    if (i >= n4) return;
    const float4* s = (const float4*)src;
    float4 acc = s[i];
    for (int p = 1; p < parts; p++) {
        float4 v = s[i + (long)p * pstride4];
        acc.x += v.x; acc.y += v.y; acc.z += v.z; acc.w += v.w;
    }
    ((float4*)dst)[i] = acc;
}

// ckv -> fp16, s-major only.  FIX (R16 crash): grid must cover exactly
// BT*128 = 524288 floats -> 512 blocks x 256 thr x 4 floats.
__global__ __launch_bounds__(256)
void cvt_kernel(const float* __restrict__ ckv, __half* __restrict__ kh)
{
    long i = ((long)blockIdx.x * 256 + threadIdx.x) * 4;
    float4 v = *(const float4*)(ckv + i);
    *(uint2*)(kh + i) = make_uint2(f2h2(v.x, v.y), f2h2(v.z, v.w));
}

// ===========================================================================
// Tiny fp32-exact precompute kernels (unchanged)
// ===========================================================================
__global__ __launch_bounds__(128)
void pk_kernel(const float* __restrict__ W_uq, const float* __restrict__ W_uk,
               float* __restrict__ P)
{
    const int i = blockIdx.x, j = threadIdx.x;
    float s = 0.f;
    #pragma unroll 8
    for (int c = 0; c < 1024; c++)
        s += W_uq[c * 128 + i] * W_uk[c * 128 + j];
    P[i * 128 + j] = s;
}
__global__ __launch_bounds__(128)
void m_kernel(const float* __restrict__ W_dq, const float* __restrict__ P,
              float* __restrict__ M)
{
    const int c = blockIdx.x, j = threadIdx.x;
    float s = 0.f;
    #pragma unroll 8
    for (int i = 0; i < 128; i++)
        s += W_dq[i * 1024 + c] * P[i * 128 + j];
    M[c * 128 + j] = s;
}
__global__ __launch_bounds__(128)
void n_kernel(const float* __restrict__ W_uq, const float* __restrict__ M,
              float* __restrict__ Nt)
{
    const int j = blockIdx.x, h = blockIdx.y, i = threadIdx.x;
    float s = 0.f;
    #pragma unroll 8
    for (int d = 0; d < 64; d++)
        s += W_uq[(h * 64 + d) * 128 + i] * M[(h * 64 + d) * 128 + j];
    Nt[(h * 128 + j) * 128 + i] = s;
}

// ===========================================================================
// fp16 mma flash attention v10: single s-major K tile; PV B-fragments via
// ldmatrix.m8n8.x4.trans (quadrant q = lane>>3 -> {s-half q&1, d-block q>>1};
// verified vs PTX fragment spec). Smem 34816 B; K gmem per tile halved.
// ===========================================================================
#define A10_WORDS (128 * 68)          // 34816 B

__global__ __launch_bounds__(128, 2)
void attn10_kernel(const __half* __restrict__ qlh, const __half* __restrict__ khG,
                   float* __restrict__ ctx)
{
    extern __shared__ uint32_t smu[];
    const int t = threadIdx.x;
    const int w = t >> 5, lid = t & 31;
    const int g = lid >> 2, tid = lid & 3;

    const int h  = blockIdx.x;               // fastest: K-tile L2 sharing
    const int qt = 31 - blockIdx.y;          // heavy q-tiles first
    const int b  = blockIdx.z;
    const long qbase = ((long)h * BT + (long)b * Tt + (long)qt * 64) * 128;

    const int rl0 = 16 * w + g;              // local query row (0..63)
    const int nkt = (qt >> 1) + 1;           // 128-key tiles

    // per-thread ldmatrix.trans base: quadrant picks {s-half, d-block parity}
    const int lq = lid >> 3, li = lid & 7;
    const uint32_t lmbase = smem_u32(smu) +
        4 * (uint32_t)((8 * (lq & 1) + li) * 68 + 4 * (lq >> 1));

    // ---- Q A-fragments: direct fp16 loads (prescaled upstream) ----
    uint32_t qf[8][4];
    {
        const __half* qr0 = qlh + qbase + (long)rl0 * 128;
        const __half* qr1 = qr0 + 8 * 128;
        #pragma unroll
        for (int kb = 0; kb < 8; kb++) {
            const int c = 16 * kb + 2 * tid;
            qf[kb][0] = *(const uint32_t*)(qr0 + c);
            qf[kb][1] = *(const uint32_t*)(qr1 + c);
            qf[kb][2] = *(const uint32_t*)(qr0 + c + 8);
            qf[kb][3] = *(const uint32_t*)(qr1 + c + 8);
        }
    }

    float oacc[16][4];
    #pragma unroll
    for (int nb = 0; nb < 16; nb++)
        #pragma unroll
        for (int q = 0; q < 4; q++) oacc[nb][q] = 0.f;

    float m_run[2] = { -1e30f, -1e30f };
    float l_run[2] = { 0.f, 0.f };

    for (int kt = 0; kt < nkt; kt++) {
        __syncthreads();
        {
            const __half* kh = khG + ((long)b * Tt + (long)kt * 128) * 128;
            #pragma unroll
            for (int i = 0; i < 16; i++) {
                int idx = t + i * 128;
                int r = idx >> 4, c = idx & 15;
                *(uint4*)(smu + r * 68 + c * 4) =
                    *(const uint4*)(kh + (long)r * 128 + c * 8);
            }
        }
        __syncthreads();

        // ---- S = Q K^T (scalar B loads, conflict-free, proven) ----
        float sacc[16][4];
        #pragma unroll
        for (int nb = 0; nb < 16; nb++)
            #pragma unroll
            for (int q = 0; q < 4; q++) sacc[nb][q] = 0.f;

        #pragma unroll
        for (int kb = 0; kb < 8; kb++) {
            const int w0 = 8 * kb + tid;
            #pragma unroll
            for (int nb = 0; nb < 16; nb++) {
                uint32_t b0 = smu[(8 * nb + g) * 68 + w0];
                uint32_t b1 = smu[(8 * nb + g) * 68 + w0 + 4];
                mma_f16(sacc[nb], qf[kb], b0, b1);
            }
        }

        // ---- causal mask (last tile only) ----
        if (kt == nkt - 1) {
            const int row0 = 64 * qt + rl0;
            #pragma unroll
            for (int nb = 0; nb < 16; nb++)
                #pragma unroll
                for (int j = 0; j < 2; j++) {
                    const int col = 128 * kt + 8 * nb + 2 * tid + j;
                    if (col > row0)     sacc[nb][j]     = -1e30f;
                    if (col > row0 + 8) sacc[nb][2 + j] = -1e30f;
                }
        }

        // ---- online softmax (exp2 domain); P stays in sacc ----
        #pragma unroll
        for (int hh = 0; hh < 2; hh++) {
            float mt = -1e30f;
            #pragma unroll
            for (int nb = 0; nb < 16; nb++)
                mt = fmaxf(mt, fmaxf(sacc[nb][2 * hh], sacc[nb][2 * hh + 1]));
            mt = fmaxf(mt, __shfl_xor_sync(0xffffffffu, mt, 1));
            mt = fmaxf(mt, __shfl_xor_sync(0xffffffffu, mt, 2));

            const float mn = fmaxf(m_run[hh], mt);
            const float sc = exp2f(m_run[hh] - mn);
            float ls = 0.f;
            #pragma unroll
            for (int nb = 0; nb < 16; nb++) {
                float p0 = exp2f(sacc[nb][2 * hh]     - mn);
                float p1 = exp2f(sacc[nb][2 * hh + 1] - mn);
                ls += p0 + p1;
                sacc[nb][2 * hh]     = p0;
                sacc[nb][2 * hh + 1] = p1;
            }
            ls += __shfl_xor_sync(0xffffffffu, ls, 1);
            ls += __shfl_xor_sync(0xffffffffu, ls, 2);
            l_run[hh] = l_run[hh] * sc + ls;
            m_run[hh] = mn;
            #pragma unroll
            for (int nb = 0; nb < 16; nb++) {
                oacc[nb][2 * hh]     *= sc;
                oacc[nb][2 * hh + 1] *= sc;
            }
        }

        // ---- O += P @ Ktile : B frags via ldmatrix.x4.trans from K1 ----
        #pragma unroll
        for (int kb = 0; kb < 8; kb++) {
            uint32_t af[4];
            af[0] = f2h2(sacc[2 * kb][0],     sacc[2 * kb][1]);
            af[1] = f2h2(sacc[2 * kb][2],     sacc[2 * kb][3]);
            af[2] = f2h2(sacc[2 * kb + 1][0], sacc[2 * kb + 1][1]);
            af[3] = f2h2(sacc[2 * kb + 1][2], sacc[2 * kb + 1][3]);
            const uint32_t kbb = lmbase + (uint32_t)kb * (16 * 68 * 4);
            #pragma unroll
            for (int nbp = 0; nbp < 8; nbp++) {
                uint32_t bm[4];
                ldsm4t(bm, kbb + (uint32_t)nbp * 32);
                mma_f16(oacc[2 * nbp],     af, bm[0], bm[1]);
                mma_f16(oacc[2 * nbp + 1], af, bm[2], bm[3]);
            }
        }
    }

    // ---- epilogue: ctx = O / l ----
    #pragma unroll
    for (int hh = 0; hh < 2; hh++) {
        const int rl = rl0 + 8 * hh;
        const float inv = 1.f / l_run[hh];
        float* dst = ctx + qbase + (long)rl * 128;
        #pragma unroll
        for (int nb = 0; nb < 16; nb++)
            *(float2*)(dst + 8 * nb + 2 * tid) =
                make_float2(oacc[nb][2 * hh] * inv, oacc[nb][2 * hh + 1] * inv);
    }
}

// ===========================================================================
extern "C" void kernel_launch(void* const* d_in, const int* in_sizes, int n_in,
                              void* d_out, int out_size)
{
    const float* x     = (const float*)d_in[0];
    const float* W_dq  = (const float*)d_in[1];
    const float* W_uq  = (const float*)d_in[2];
    const float* W_dkv = (const float*)d_in[3];
    const float* W_uk  = (const float*)d_in[4];
    const float* W_uv  = (const float*)d_in[5];
    const float* W_o   = (const float*)d_in[6];

    float* y   = (float*)d_out;
    float* ckv = y + (long)BT * Cc;

    float *P, *M, *Nt, *R, *Aq, *QLp, *CT;
    __half *KH;
    cudaGetSymbolAddress((void**)&P,  g_P);
    cudaGetSymbolAddress((void**)&M,  g_M);
    cudaGetSymbolAddress((void**)&Nt, g_Nt);
    cudaGetSymbolAddress((void**)&R,  g_R);
    cudaGetSymbolAddress((void**)&Aq, g_Aq);
    cudaGetSymbolAddress((void**)&QLp, g_ql);
    cudaGetSymbolAddress((void**)&CT, g_ct);
    cudaGetSymbolAddress((void**)&KH,  g_kh);

    const int NONE = 1 << 30;
    const size_t S64   = 2 * (128 * 20 + 64 * 20) * 4;        // 30720
    const size_t S128  = 2 * (128 * 20 + 128 * 20) * 4;       // 40960
    const size_t S64C  = 2 * 2 * (128 * 20 + 64 * 20) * 4;    // 61440

    cudaFuncSetAttribute((const void*)hgemm<64, false, true, false>,
                         cudaFuncAttributeMaxDynamicSharedMemorySize, (int)S64C);
    cudaFuncSetAttribute((const void*)hgemm<128, false, false, true>,
                         cudaFuncAttributeMaxDynamicSharedMemorySize, (int)S128);
    cudaFuncSetAttribute((const void*)hgemm<64, true, false, false>,
                         cudaFuncAttributeMaxDynamicSharedMemorySize, (int)S64);
    cudaFuncSetAttribute((const void*)hgemm<64, false, false, false>,
                         cudaFuncAttributeMaxDynamicSharedMemorySize, (int)S64);

    // Exact fp32 precompute chain: P -> M -> Nt
    pk_kernel<<<128, 128>>>(W_uq, W_uk, P);
    m_kernel<<<1024, 128>>>(W_dq, P, M);
    n_kernel<<<dim3(128, 16), 128>>>(W_uq, M, Nt);

    // Fused x-GEMM (fp16 compensated), split-K=2
    {
        const long PS = (long)BT * 128;
        hgemm<64, false, true, false><<<dim3(32, 4, 2), 256, S64C>>>(
            x, W_dq, CT, W_dkv, CT + 2 * PS, 512,
            1024, 1024, 128, 512, 512, PS, 2, 1.f);
        reduce_add<<<512, 256>>>(CT,          Aq,  (int)(PS / 4), 2, PS / 4);
        reduce_add<<<512, 256>>>(CT + 2 * PS, ckv, (int)(PS / 4), 2, PS / 4);
    }

    // ckv -> fp16, s-major only (grid 512 covers exactly BT*128 floats)
    cvt_kernel<<<512, 256>>>(ckv, KH);

    // R = W_o @ W_uv (fp16 NN), split-K=4
    {
        const long PR = 1024 * 128;
        hgemm<64, true, false, false><<<dim3(8, 2, 4), 256, S64>>>(
            W_o, W_uv, CT, nullptr, nullptr, 256,
            1024, 128, 128, 256, 256 * 128, PR, NONE, 1.f);
        reduce_add<<<128, 256>>>(CT, R, (int)(PR / 4), 4, PR / 4);
    }

    // ql[h] = Aq @ N[h] -> fp16, prescaled by 0.125*log2(e)
    // (sC in FLOAT units: BT*128 halves == BT*128/2 floats)
    hgemm<128, false, false, true><<<dim3(32, 1, 16), 256, S128>>>(
        Aq, Nt, QLp, nullptr, nullptr, 128, 128, 128, 128,
        0, 128 * 128, (long)BT * 128 / 2, NONE, QSCALE);

    // fp16 flash attention v10 -> ctx
    cudaFuncSetAttribute(attn10_kernel, cudaFuncAttributeMaxDynamicSharedMemorySize,
                         A10_WORDS * 4);
    attn10_kernel<<<dim3(16, 32, 2), 128, A10_WORDS * 4>>>(
        (const __half*)QLp, KH, CT);

    // y[:, h*64:] = ctx[h] @ R[h*64:, :]^T   (fp16, batched 16, K=128, N=64)
    hgemm<64, false, false, false><<<dim3(32, 1, 16), 256, S64>>>(
        CT, R, y, nullptr, nullptr, 128, 128, 128, 1024,
        (long)BT * 128, 64 * 128, 64, NONE, 1.f);
}